// round 8
// baseline (speedup 1.0000x reference)
#include <cuda_runtime.h>
#include <cstdint>

#define KC    8192
#define DIM   64
#define NROWS 32768
#define BM    64      // rows per block
#define BK    128     // codes per smem chunk
#define NCHUNK (KC / BK)
#define THREADS 512

// smem: x 64*64 + cb 2*128*64 + best 4*64 (d) + 4*64 (i)
#define SMEM_BYTES ((BM*DIM + 2*BK*DIM + 8*BM) * 4)

__device__ float g_e2[KC];

// ---------------- helpers ----------------
__device__ __forceinline__ unsigned long long ffma2(unsigned long long a,
                                                    unsigned long long b,
                                                    unsigned long long c) {
    unsigned long long d;
    asm("fma.rn.f32x2 %0, %1, %2, %3;" : "=l"(d) : "l"(a), "l"(b), "l"(c));
    return d;
}
__device__ __forceinline__ float f2lo(unsigned long long v) {
    return __uint_as_float((unsigned)v);
}
__device__ __forceinline__ float f2hi(unsigned long long v) {
    return __uint_as_float((unsigned)(v >> 32));
}
__device__ __forceinline__ void cp_async16(void* dst, const void* src) {
    unsigned s = (unsigned)__cvta_generic_to_shared(dst);
    asm volatile("cp.async.cg.shared.global [%0], [%1], 16;" :: "r"(s), "l"(src));
}
__device__ __forceinline__ void cp_commit() {
    asm volatile("cp.async.commit_group;");
}

// ---------------- e2 = ||codebook_k||^2 ----------------
__global__ void e2_kernel(const float* __restrict__ cb) {
    int k = blockIdx.x * blockDim.x + threadIdx.x;
    if (k >= KC) return;
    const float4* p = reinterpret_cast<const float4*>(cb + (size_t)k * DIM);
    float s = 0.f;
#pragma unroll
    for (int i = 0; i < DIM / 4; i++) {
        float4 v = p[i];
        s += v.x * v.x + v.y * v.y + v.z * v.z + v.w * v.w;
    }
    g_e2[k] = s;
}

// ---------------- main VQ kernel ----------------
// 512 threads, 16 warps. Warp tile: 16 rows x 32 codes.
// wg_r = warp>>2 (4 row groups of 16), wg_c = warp&3 (4 code groups of 32).
// Lanes: cl = lane>>2 (8 code-lanes), rl = lane&3 (4 row-lanes).
// Thread tile: 4 rows x 4 codes. XOR-swizzled smem, no padding.
__global__ void __launch_bounds__(THREADS, 1)
vq_kernel(const float* __restrict__ x,
          const float* __restrict__ cb,
          float* __restrict__ out_q,
          float* __restrict__ out_idx,
          int write_idx) {
    extern __shared__ float smem[];
    float* x_s   = smem;                      // BM*DIM
    float* cb_s0 = smem + BM * DIM;           // BK*DIM
    float* cb_s1 = cb_s0 + BK * DIM;          // BK*DIM
    float* s_d   = cb_s1 + BK * DIM;          // 4*BM
    int*   s_i   = (int*)(s_d + 4 * BM);      // 4*BM

    const int tid   = threadIdx.x;
    const int lane  = tid & 31;
    const int warp  = tid >> 5;
    const int rl    = lane & 3;
    const int cl    = lane >> 2;
    const int wg_r  = warp >> 2;          // 4 row groups of 16 rows
    const int wg_c  = warp & 3;           // 4 code groups of 32 codes
    const int rowbase = wg_r * 16;
    const int row0  = blockIdx.x * BM;

    // ---- stage: x tile (swizzled) + cb chunk 0 ----
#pragma unroll
    for (int i = 0; i < 2; i++) {
        int j = i * THREADS + tid;
        int row = j >> 4, q = j & 15;
        cp_async16(x_s + row * DIM + ((q ^ (row & 3)) << 2),
                   x + (size_t)(row0 + row) * DIM + q * 4);
    }
#pragma unroll
    for (int i = 0; i < 4; i++) {
        int j = i * THREADS + tid;
        int code = j >> 4, q = j & 15;
        cp_async16(cb_s0 + code * DIM + ((q ^ (code & 15)) << 2),
                   cb + (size_t)code * DIM + q * 4);
    }
    cp_commit();
#pragma unroll
    for (int i = 0; i < 4; i++) {
        int j = i * THREADS + tid;
        int code = j >> 4, q = j & 15;
        cp_async16(cb_s1 + code * DIM + ((q ^ (code & 15)) << 2),
                   cb + (size_t)(BK + code) * DIM + q * 4);
    }
    cp_commit();

    float bestd[4];
    int   besti[4];
#pragma unroll
    for (int r = 0; r < 4; r++) { bestd[r] = __int_as_float(0x7f800000); besti[r] = 0; }

    const float* xp = x_s + (rowbase + rl) * DIM;   // row = rowbase + rl + 4*rr

    for (int t = 0; t < NCHUNK; t++) {
        asm volatile("cp.async.wait_group 1;");
        __syncthreads();
        const float* cbuf = (t & 1) ? cb_s1 : cb_s0;
        const float* cpp  = cbuf + (wg_c * 32 + cl) * DIM;   // code = wg_c*32 + cl + 8*cc

        unsigned long long acc[4][4];
#pragma unroll
        for (int r = 0; r < 4; r++)
#pragma unroll
            for (int c = 0; c < 4; c++) acc[r][c] = 0ull;

#pragma unroll
        for (int u = 0; u < 16; u++) {           // 16B unit along D
            const int sux = (u ^ rl) << 2;       // float offset of swizzled unit
            ulonglong2 xv[4];
#pragma unroll
            for (int rr = 0; rr < 4; rr++)
                xv[rr] = *reinterpret_cast<const ulonglong2*>(xp + rr * 4 * DIM + sux);
            const int su0 = (u ^ cl) << 2;
            ulonglong2 cv[4];
#pragma unroll
            for (int cc = 0; cc < 4; cc++) {
                int su = (cc & 1) ? (su0 ^ 32) : su0;   // code bit3 flips swizzle bit
                cv[cc] = *reinterpret_cast<const ulonglong2*>(cpp + cc * 8 * DIM + su);
            }
#pragma unroll
            for (int rr = 0; rr < 4; rr++)
#pragma unroll
                for (int cc = 0; cc < 4; cc++) {
                    acc[rr][cc] = ffma2(xv[rr].x, cv[cc].x, acc[rr][cc]);
                    acc[rr][cc] = ffma2(xv[rr].y, cv[cc].y, acc[rr][cc]);
                }
        }

        __syncthreads();   // everyone done reading this buffer
        if (t + 2 < NCHUNK) {
            float* dst = (t & 1) ? cb_s1 : cb_s0;
#pragma unroll
            for (int i = 0; i < 4; i++) {
                int j = i * THREADS + tid;
                int code = j >> 4, q = j & 15;
                cp_async16(dst + code * DIM + ((q ^ (code & 15)) << 2),
                           cb + (size_t)((t + 2) * BK + code) * DIM + q * 4);
            }
        }
        cp_commit();  // empty group legal on last two iterations

        // finalize this chunk's codes (ascending in cc -> strict < keeps lowest idx)
        const int cbase = t * BK + wg_c * 32;
#pragma unroll
        for (int cc = 0; cc < 4; cc++) {
            int code = cbase + cl + 8 * cc;
            float e2v = __ldg(g_e2 + code);
#pragma unroll
            for (int rr = 0; rr < 4; rr++) {
                float dot  = f2lo(acc[rr][cc]) + f2hi(acc[rr][cc]);
                float dist = fmaf(-2.f, dot, e2v);
                if (dist < bestd[rr]) { bestd[rr] = dist; besti[rr] = code; }
            }
        }
    }

    // ---- argmin reduce across the 8 code-lanes (lane bits 2..4) ----
#pragma unroll
    for (int m = 16; m >= 4; m >>= 1) {
#pragma unroll
        for (int rr = 0; rr < 4; rr++) {
            float od = __shfl_xor_sync(0xffffffffu, bestd[rr], m);
            int   oi = __shfl_xor_sync(0xffffffffu, besti[rr], m);
            if (od < bestd[rr] || (od == bestd[rr] && oi < besti[rr])) {
                bestd[rr] = od; besti[rr] = oi;
            }
        }
    }
    // lanes 0..3 (cl==0) hold rows rowbase + lane + 4*rr for this warp's code group
    if (lane < 4) {
#pragma unroll
        for (int rr = 0; rr < 4; rr++) {
            int r = rowbase + lane + 4 * rr;
            s_d[wg_c * BM + r] = bestd[rr];
            s_i[wg_c * BM + r] = besti[rr];
        }
    }
    __syncthreads();

    // combine the 4 code groups per row (64 threads)
    if (tid < BM) {
        float bd = s_d[tid];
        int   bi = s_i[tid];
#pragma unroll
        for (int g = 1; g < 4; g++) {
            float od = s_d[g * BM + tid];
            int   oi = s_i[g * BM + tid];
            if (od < bd || (od == bd && oi < bi)) { bd = od; bi = oi; }
        }
        s_i[tid] = bi;
        if (write_idx) out_idx[row0 + tid] = (float)bi;
    }
    __syncthreads();

    // cooperative coalesced gather of codebook rows -> x_q
#pragma unroll
    for (int i = 0; i < 2; i++) {
        int j = i * THREADS + tid;
        int row = j >> 4, q = j & 15;
        float4 v = __ldg(reinterpret_cast<const float4*>(cb + (size_t)s_i[row] * DIM) + q);
        reinterpret_cast<float4*>(out_q + (size_t)(row0 + row) * DIM)[q] = v;
    }
}

extern "C" void kernel_launch(void* const* d_in, const int* in_sizes, int n_in,
                              void* d_out, int out_size) {
    const float* x  = (const float*)d_in[0];
    const float* cb = (const float*)d_in[1];
    if (n_in >= 2 && in_sizes[0] == KC * DIM && in_sizes[1] == NROWS * DIM) {
        const float* tmp = x; x = cb; cb = tmp;
    }
    float* out = (float*)d_out;
    int write_idx = (out_size >= NROWS * DIM + NROWS) ? 1 : 0;

    cudaFuncSetAttribute(vq_kernel, cudaFuncAttributeMaxDynamicSharedMemorySize, SMEM_BYTES);

    e2_kernel<<<KC / 256, 256>>>(cb);
    vq_kernel<<<NROWS / BM, THREADS, SMEM_BYTES>>>(x, cb, out, out + (size_t)NROWS * DIM, write_idx);
}

// round 13
// speedup vs baseline: 1.1161x; 1.1161x over previous
#include <cuda_runtime.h>
#include <cstdint>

#define KC    8192
#define DIM   64
#define NROWS 32768
#define BM    64      // rows per block
#define BK    128     // codes per smem chunk
#define NCHUNK (KC / BK)
#define THREADS 256

// smem: x 64*64 + cb 2*128*64 + best 64+64
#define SMEM_BYTES ((BM*DIM + 2*BK*DIM + 2*BM) * 4)

__device__ float g_e2[KC];

// ---------------- helpers ----------------
__device__ __forceinline__ unsigned long long ffma2(unsigned long long a,
                                                    unsigned long long b,
                                                    unsigned long long c) {
    unsigned long long d;
    asm("fma.rn.f32x2 %0, %1, %2, %3;" : "=l"(d) : "l"(a), "l"(b), "l"(c));
    return d;
}
__device__ __forceinline__ float f2lo(unsigned long long v) {
    return __uint_as_float((unsigned)v);
}
__device__ __forceinline__ float f2hi(unsigned long long v) {
    return __uint_as_float((unsigned)(v >> 32));
}
__device__ __forceinline__ void cp_async16(void* dst, const void* src) {
    unsigned s = (unsigned)__cvta_generic_to_shared(dst);
    asm volatile("cp.async.cg.shared.global [%0], [%1], 16;" :: "r"(s), "l"(src));
}
__device__ __forceinline__ void cp_commit() {
    asm volatile("cp.async.commit_group;");
}

// ---------------- e2 = ||codebook_k||^2 ----------------
__global__ void e2_kernel(const float* __restrict__ cb) {
    int k = blockIdx.x * blockDim.x + threadIdx.x;
    if (k >= KC) return;
    const float4* p = reinterpret_cast<const float4*>(cb + (size_t)k * DIM);
    float s = 0.f;
#pragma unroll
    for (int i = 0; i < DIM / 4; i++) {
        float4 v = p[i];
        s += v.x * v.x + v.y * v.y + v.z * v.z + v.w * v.w;
    }
    g_e2[k] = s;
}

// ---------------- main VQ kernel ----------------
// 256 threads, 8 warps. Warp tile: 16 rows x 64 codes.
// wg_r = warp>>1 (4 row groups of 16), wg_c = warp&1 (2 code groups of 64).
// Lanes: cl = lane>>2 (8 code-lanes), rl = lane&3 (4 row-lanes).
// Thread tile: 4 rows x 8 codes. XOR-swizzled smem, no padding.
// Inner u-loop explicitly software-pipelined (ping-pong register buffers).
__global__ void __launch_bounds__(THREADS, 1)
vq_kernel(const float* __restrict__ x,
          const float* __restrict__ cb,
          float* __restrict__ out_q,
          float* __restrict__ out_idx,
          int write_idx) {
    extern __shared__ float smem[];
    float* x_s   = smem;                      // BM*DIM
    float* cb_s0 = smem + BM * DIM;           // BK*DIM
    float* cb_s1 = cb_s0 + BK * DIM;          // BK*DIM
    float* s_d   = cb_s1 + BK * DIM;          // BM
    int*   s_i   = (int*)(s_d + BM);          // BM

    const int tid   = threadIdx.x;
    const int lane  = tid & 31;
    const int warp  = tid >> 5;
    const int rl    = lane & 3;
    const int cl    = lane >> 2;
    const int wg_r  = warp >> 1;          // 4 row groups of 16 rows
    const int wg_c  = warp & 1;           // 2 code groups of 64 codes
    const int rowbase = wg_r * 16;
    const int row0  = blockIdx.x * BM;

    // ---- stage: x tile (swizzled) + cb chunk 0 ----
#pragma unroll
    for (int i = 0; i < 4; i++) {
        int j = i * THREADS + tid;
        int row = j >> 4, q = j & 15;
        cp_async16(x_s + row * DIM + ((q ^ (row & 3)) << 2),
                   x + (size_t)(row0 + row) * DIM + q * 4);
    }
#pragma unroll
    for (int i = 0; i < 8; i++) {
        int j = i * THREADS + tid;
        int code = j >> 4, q = j & 15;
        cp_async16(cb_s0 + code * DIM + ((q ^ (code & 15)) << 2),
                   cb + (size_t)code * DIM + q * 4);
    }
    cp_commit();
#pragma unroll
    for (int i = 0; i < 8; i++) {
        int j = i * THREADS + tid;
        int code = j >> 4, q = j & 15;
        cp_async16(cb_s1 + code * DIM + ((q ^ (code & 15)) << 2),
                   cb + (size_t)(BK + code) * DIM + q * 4);
    }
    cp_commit();

    float bestd[4];
    int   besti[4];
#pragma unroll
    for (int r = 0; r < 4; r++) { bestd[r] = __int_as_float(0x7f800000); besti[r] = 0; }

    const float* xp = x_s + (rowbase + rl) * DIM;   // row = rowbase + rl + 4*rr

    for (int t = 0; t < NCHUNK; t++) {
        asm volatile("cp.async.wait_group 1;");
        __syncthreads();
        const float* cbuf = (t & 1) ? cb_s1 : cb_s0;
        const float* cpp  = cbuf + (wg_c * 64 + cl) * DIM;   // code = wg_c*64 + cl + 8*cc

        unsigned long long acc[4][8];
#pragma unroll
        for (int r = 0; r < 4; r++)
#pragma unroll
            for (int c = 0; c < 8; c++) acc[r][c] = 0ull;

        // ---- software-pipelined u-loop: ping-pong load buffers ----
        ulonglong2 xvb[2][4];
        ulonglong2 cvb[2][8];
        {   // prefetch u = 0 into buffer 0
            const int sux = (0 ^ rl) << 2;
#pragma unroll
            for (int rr = 0; rr < 4; rr++)
                xvb[0][rr] = *reinterpret_cast<const ulonglong2*>(xp + rr * 4 * DIM + sux);
            const int su0 = (0 ^ cl) << 2;
#pragma unroll
            for (int cc = 0; cc < 8; cc++) {
                int su = (cc & 1) ? (su0 ^ 32) : su0;
                cvb[0][cc] = *reinterpret_cast<const ulonglong2*>(cpp + cc * 8 * DIM + su);
            }
        }
#pragma unroll
        for (int u = 0; u < 16; u++) {
            const int cur = u & 1;
            const int nxt = cur ^ 1;
            if (u < 15) {   // prefetch u+1 before consuming u
                const int sux = ((u + 1) ^ rl) << 2;
#pragma unroll
                for (int rr = 0; rr < 4; rr++)
                    xvb[nxt][rr] = *reinterpret_cast<const ulonglong2*>(xp + rr * 4 * DIM + sux);
                const int su0 = ((u + 1) ^ cl) << 2;
#pragma unroll
                for (int cc = 0; cc < 8; cc++) {
                    int su = (cc & 1) ? (su0 ^ 32) : su0;
                    cvb[nxt][cc] = *reinterpret_cast<const ulonglong2*>(cpp + cc * 8 * DIM + su);
                }
            }
#pragma unroll
            for (int rr = 0; rr < 4; rr++)
#pragma unroll
                for (int cc = 0; cc < 8; cc++) {
                    acc[rr][cc] = ffma2(xvb[cur][rr].x, cvb[cur][cc].x, acc[rr][cc]);
                    acc[rr][cc] = ffma2(xvb[cur][rr].y, cvb[cur][cc].y, acc[rr][cc]);
                }
        }

        __syncthreads();   // everyone done reading this buffer
        if (t + 2 < NCHUNK) {
            float* dst = (t & 1) ? cb_s1 : cb_s0;
#pragma unroll
            for (int i = 0; i < 8; i++) {
                int j = i * THREADS + tid;
                int code = j >> 4, q = j & 15;
                cp_async16(dst + code * DIM + ((q ^ (code & 15)) << 2),
                           cb + (size_t)((t + 2) * BK + code) * DIM + q * 4);
            }
        }
        cp_commit();  // empty group legal on last two iterations

        // finalize this chunk's codes (ascending in cc -> strict < keeps lowest idx)
        const int cbase = t * BK + wg_c * 64;
#pragma unroll
        for (int cc = 0; cc < 8; cc++) {
            int code = cbase + cl + 8 * cc;
            float e2v = __ldg(g_e2 + code);
#pragma unroll
            for (int rr = 0; rr < 4; rr++) {
                float dot  = f2lo(acc[rr][cc]) + f2hi(acc[rr][cc]);
                float dist = fmaf(-2.f, dot, e2v);
                if (dist < bestd[rr]) { bestd[rr] = dist; besti[rr] = code; }
            }
        }
    }

    // ---- argmin reduce across the 8 code-lanes (lane bits 2..4) ----
#pragma unroll
    for (int m = 16; m >= 4; m >>= 1) {
#pragma unroll
        for (int rr = 0; rr < 4; rr++) {
            float od = __shfl_xor_sync(0xffffffffu, bestd[rr], m);
            int   oi = __shfl_xor_sync(0xffffffffu, besti[rr], m);
            if (od < bestd[rr] || (od == bestd[rr] && oi < besti[rr])) {
                bestd[rr] = od; besti[rr] = oi;
            }
        }
    }
    // lanes 0..3 (cl==0) hold rows rowbase + lane + 4*rr for this warp's codes
    if (wg_c == 0 && lane < 4) {
#pragma unroll
        for (int rr = 0; rr < 4; rr++) {
            int r = rowbase + lane + 4 * rr;
            s_d[r] = bestd[rr]; s_i[r] = besti[rr];
        }
    }
    __syncthreads();
    if (wg_c == 1 && lane < 4) {
#pragma unroll
        for (int rr = 0; rr < 4; rr++) {
            int r = rowbase + lane + 4 * rr;
            if (bestd[rr] < s_d[r] || (bestd[rr] == s_d[r] && besti[rr] < s_i[r])) {
                s_d[r] = bestd[rr]; s_i[r] = besti[rr];
            }
        }
    }
    __syncthreads();

    if (write_idx && tid < BM) out_idx[row0 + tid] = (float)s_i[tid];

    // cooperative coalesced gather of codebook rows -> x_q
#pragma unroll
    for (int i = 0; i < 4; i++) {
        int j = i * THREADS + tid;
        int row = j >> 4, q = j & 15;
        float4 v = __ldg(reinterpret_cast<const float4*>(cb + (size_t)s_i[row] * DIM) + q);
        reinterpret_cast<float4*>(out_q + (size_t)(row0 + row) * DIM)[q] = v;
    }
}

extern "C" void kernel_launch(void* const* d_in, const int* in_sizes, int n_in,
                              void* d_out, int out_size) {
    const float* x  = (const float*)d_in[0];
    const float* cb = (const float*)d_in[1];
    if (n_in >= 2 && in_sizes[0] == KC * DIM && in_sizes[1] == NROWS * DIM) {
        const float* tmp = x; x = cb; cb = tmp;
    }
    float* out = (float*)d_out;
    int write_idx = (out_size >= NROWS * DIM + NROWS) ? 1 : 0;

    cudaFuncSetAttribute(vq_kernel, cudaFuncAttributeMaxDynamicSharedMemorySize, SMEM_BYTES);

    e2_kernel<<<KC / 256, 256>>>(cb);
    vq_kernel<<<NROWS / BM, THREADS, SMEM_BYTES>>>(x, cb, out, out + (size_t)NROWS * DIM, write_idx);
}

// round 14
// speedup vs baseline: 1.2062x; 1.0807x over previous
#include <cuda_runtime.h>
#include <cstdint>

#define KC    8192
#define DIM   64
#define NROWS 32768
#define BM    128     // rows per block
#define BK    128     // codes per smem chunk
#define NCHUNK (KC / BK)
#define THREADS 256

// smem: x 128*64 + cb 2*128*64 + best 128+128
#define SMEM_BYTES ((BM*DIM + 2*BK*DIM + 2*BM) * 4)

__device__ float g_e2[KC];

// ---------------- helpers ----------------
__device__ __forceinline__ unsigned long long ffma2(unsigned long long a,
                                                    unsigned long long b,
                                                    unsigned long long c) {
    unsigned long long d;
    asm("fma.rn.f32x2 %0, %1, %2, %3;" : "=l"(d) : "l"(a), "l"(b), "l"(c));
    return d;
}
__device__ __forceinline__ float f2lo(unsigned long long v) {
    return __uint_as_float((unsigned)v);
}
__device__ __forceinline__ float f2hi(unsigned long long v) {
    return __uint_as_float((unsigned)(v >> 32));
}
__device__ __forceinline__ void cp_async16(void* dst, const void* src) {
    unsigned s = (unsigned)__cvta_generic_to_shared(dst);
    asm volatile("cp.async.cg.shared.global [%0], [%1], 16;" :: "r"(s), "l"(src));
}
__device__ __forceinline__ void cp_commit() {
    asm volatile("cp.async.commit_group;");
}

// ---------------- e2 = ||codebook_k||^2 ----------------
__global__ void e2_kernel(const float* __restrict__ cb) {
    int k = blockIdx.x * blockDim.x + threadIdx.x;
    if (k >= KC) return;
    const float4* p = reinterpret_cast<const float4*>(cb + (size_t)k * DIM);
    float s = 0.f;
#pragma unroll
    for (int i = 0; i < DIM / 4; i++) {
        float4 v = p[i];
        s += v.x * v.x + v.y * v.y + v.z * v.z + v.w * v.w;
    }
    g_e2[k] = s;
}

// ---------------- main VQ kernel ----------------
// 256 threads, 8 warps. Warp tile: 32 rows x 64 codes.
// wg_r = warp>>1 (4 row groups of 32), wg_c = warp&1 (2 code groups of 64).
// Lanes: cl = lane>>2 (8 code-lanes), rl = lane&3 (4 row-lanes).
// Thread tile: 8 rows x 8 codes -> 128 FFMA2 per 16 LDS.128 per u-step.
// XOR-swizzled smem, no padding.
__global__ void __launch_bounds__(THREADS, 1)
vq_kernel(const float* __restrict__ x,
          const float* __restrict__ cb,
          float* __restrict__ out_q,
          float* __restrict__ out_idx,
          int write_idx) {
    extern __shared__ float smem[];
    float* x_s   = smem;                      // BM*DIM
    float* cb_s0 = smem + BM * DIM;           // BK*DIM
    float* cb_s1 = cb_s0 + BK * DIM;          // BK*DIM
    float* s_d   = cb_s1 + BK * DIM;          // BM
    int*   s_i   = (int*)(s_d + BM);          // BM

    const int tid   = threadIdx.x;
    const int lane  = tid & 31;
    const int warp  = tid >> 5;
    const int rl    = lane & 3;
    const int cl    = lane >> 2;
    const int wg_r  = warp >> 1;          // 4 row groups of 32 rows
    const int wg_c  = warp & 1;           // 2 code groups of 64 codes
    const int rowbase = wg_r * 32;
    const int row0  = blockIdx.x * BM;

    // ---- stage: x tile (swizzled) + cb chunk 0 ----
#pragma unroll
    for (int i = 0; i < 8; i++) {
        int j = i * THREADS + tid;
        int row = j >> 4, q = j & 15;
        cp_async16(x_s + row * DIM + ((q ^ (row & 3)) << 2),
                   x + (size_t)(row0 + row) * DIM + q * 4);
    }
#pragma unroll
    for (int i = 0; i < 8; i++) {
        int j = i * THREADS + tid;
        int code = j >> 4, q = j & 15;
        cp_async16(cb_s0 + code * DIM + ((q ^ (code & 15)) << 2),
                   cb + (size_t)code * DIM + q * 4);
    }
    cp_commit();
#pragma unroll
    for (int i = 0; i < 8; i++) {
        int j = i * THREADS + tid;
        int code = j >> 4, q = j & 15;
        cp_async16(cb_s1 + code * DIM + ((q ^ (code & 15)) << 2),
                   cb + (size_t)(BK + code) * DIM + q * 4);
    }
    cp_commit();

    float bestd[8];
    int   besti[8];
#pragma unroll
    for (int r = 0; r < 8; r++) { bestd[r] = __int_as_float(0x7f800000); besti[r] = 0; }

    const float* xp = x_s + (rowbase + rl) * DIM;   // row = rowbase + rl + 4*rr

    for (int t = 0; t < NCHUNK; t++) {
        asm volatile("cp.async.wait_group 1;");
        __syncthreads();
        const float* cbuf = (t & 1) ? cb_s1 : cb_s0;
        const float* cpp  = cbuf + (wg_c * 64 + cl) * DIM;   // code = wg_c*64 + cl + 8*cc

        unsigned long long acc[8][8];
#pragma unroll
        for (int r = 0; r < 8; r++)
#pragma unroll
            for (int c = 0; c < 8; c++) acc[r][c] = 0ull;

#pragma unroll
        for (int u = 0; u < 16; u++) {           // 16B unit along D
            const int sux = (u ^ rl) << 2;       // float offset of swizzled unit
            ulonglong2 xv[8];
#pragma unroll
            for (int rr = 0; rr < 8; rr++)
                xv[rr] = *reinterpret_cast<const ulonglong2*>(xp + rr * 4 * DIM + sux);
            const int su0 = (u ^ cl) << 2;
            ulonglong2 cv[8];
#pragma unroll
            for (int cc = 0; cc < 8; cc++) {
                int su = (cc & 1) ? (su0 ^ 32) : su0;   // code bit3 flips swizzle bit
                cv[cc] = *reinterpret_cast<const ulonglong2*>(cpp + cc * 8 * DIM + su);
            }
#pragma unroll
            for (int rr = 0; rr < 8; rr++)
#pragma unroll
                for (int cc = 0; cc < 8; cc++) {
                    acc[rr][cc] = ffma2(xv[rr].x, cv[cc].x, acc[rr][cc]);
                    acc[rr][cc] = ffma2(xv[rr].y, cv[cc].y, acc[rr][cc]);
                }
        }

        __syncthreads();   // everyone done reading this buffer
        if (t + 2 < NCHUNK) {
            float* dst = (t & 1) ? cb_s1 : cb_s0;
#pragma unroll
            for (int i = 0; i < 8; i++) {
                int j = i * THREADS + tid;
                int code = j >> 4, q = j & 15;
                cp_async16(dst + code * DIM + ((q ^ (code & 15)) << 2),
                           cb + (size_t)((t + 2) * BK + code) * DIM + q * 4);
            }
        }
        cp_commit();  // empty group legal on last two iterations

        // finalize this chunk's codes (ascending in cc -> strict < keeps lowest idx)
        const int cbase = t * BK + wg_c * 64;
#pragma unroll
        for (int cc = 0; cc < 8; cc++) {
            int code = cbase + cl + 8 * cc;
            float e2v = __ldg(g_e2 + code);
#pragma unroll
            for (int rr = 0; rr < 8; rr++) {
                float dot  = f2lo(acc[rr][cc]) + f2hi(acc[rr][cc]);
                float dist = fmaf(-2.f, dot, e2v);
                if (dist < bestd[rr]) { bestd[rr] = dist; besti[rr] = code; }
            }
        }
    }

    // ---- argmin reduce across the 8 code-lanes (lane bits 2..4) ----
#pragma unroll
    for (int m = 16; m >= 4; m >>= 1) {
#pragma unroll
        for (int rr = 0; rr < 8; rr++) {
            float od = __shfl_xor_sync(0xffffffffu, bestd[rr], m);
            int   oi = __shfl_xor_sync(0xffffffffu, besti[rr], m);
            if (od < bestd[rr] || (od == bestd[rr] && oi < besti[rr])) {
                bestd[rr] = od; besti[rr] = oi;
            }
        }
    }
    // lanes 0..3 (cl==0) hold rows rowbase + lane + 4*rr for this warp's codes
    if (wg_c == 0 && lane < 4) {
#pragma unroll
        for (int rr = 0; rr < 8; rr++) {
            int r = rowbase + lane + 4 * rr;
            s_d[r] = bestd[rr]; s_i[r] = besti[rr];
        }
    }
    __syncthreads();
    if (wg_c == 1 && lane < 4) {
#pragma unroll
        for (int rr = 0; rr < 8; rr++) {
            int r = rowbase + lane + 4 * rr;
            if (bestd[rr] < s_d[r] || (bestd[rr] == s_d[r] && besti[rr] < s_i[r])) {
                s_d[r] = bestd[rr]; s_i[r] = besti[rr];
            }
        }
    }
    __syncthreads();

    if (write_idx && tid < BM) out_idx[row0 + tid] = (float)s_i[tid];

    // cooperative coalesced gather of codebook rows -> x_q
#pragma unroll
    for (int i = 0; i < 8; i++) {
        int j = i * THREADS + tid;
        int row = j >> 4, q = j & 15;
        float4 v = __ldg(reinterpret_cast<const float4*>(cb + (size_t)s_i[row] * DIM) + q);
        reinterpret_cast<float4*>(out_q + (size_t)(row0 + row) * DIM)[q] = v;
    }
}

extern "C" void kernel_launch(void* const* d_in, const int* in_sizes, int n_in,
                              void* d_out, int out_size) {
    const float* x  = (const float*)d_in[0];
    const float* cb = (const float*)d_in[1];
    if (n_in >= 2 && in_sizes[0] == KC * DIM && in_sizes[1] == NROWS * DIM) {
        const float* tmp = x; x = cb; cb = tmp;
    }
    float* out = (float*)d_out;
    int write_idx = (out_size >= NROWS * DIM + NROWS) ? 1 : 0;

    cudaFuncSetAttribute(vq_kernel, cudaFuncAttributeMaxDynamicSharedMemorySize, SMEM_BYTES);

    e2_kernel<<<KC / 256, 256>>>(cb);
    vq_kernel<<<NROWS / BM, THREADS, SMEM_BYTES>>>(x, cb, out, out + (size_t)NROWS * DIM, write_idx);
}